// round 6
// baseline (speedup 1.0000x reference)
#include <cuda_runtime.h>
#include <cuda_fp16.h>
#include <math.h>
#include <stdint.h>

// Problem constants
#define Lq 12
#define Eq 1024
#define Hq 16
#define Tq 512
#define Bq 8
#define Vq 512
#define Fq 4096
#define Dq 64
#define Mq (Bq*Tq)   // 4096 rows

// ---------------- scratch (static device globals; allocation-free) ----------
__device__ float g_h  [Mq*Eq];
__device__ float g_q  [Mq*Eq];
__device__ float g_k  [Mq*Eq];
__device__ float g_v  [Mq*Eq];
__device__ float g_att[(size_t)Bq*Hq*Tq*Tq];   // 134 MB

// fp16 hi/lo activations
__device__ __half g_xn_hi[Mq*Eq],  g_xn_lo[Mq*Eq];
__device__ __half g_y_hi [Mq*Eq],  g_y_lo [Mq*Eq];
__device__ __half g_ml_hi[(size_t)Mq*Fq], g_ml_lo[(size_t)Mq*Fq];

// fp16 transposed weights [l][N][K] (hi only)
__device__ __half g_wq[(size_t)Lq*Eq*Eq];
__device__ __half g_wk[(size_t)Lq*Eq*Eq];
__device__ __half g_wv[(size_t)Lq*Eq*Eq];
__device__ __half g_wp[(size_t)Lq*Eq*Eq];
__device__ __half g_w1[(size_t)Lq*Eq*Fq];
__device__ __half g_w2[(size_t)Lq*Fq*Eq];
__device__ __half g_wh[(size_t)Eq*Vq];

// ================= PTX helpers (baseline targets only) ======================
__device__ __forceinline__ uint32_t smem_u32(const void* p) {
    uint32_t a;
    asm("{ .reg .u64 t; cvta.to.shared.u64 t, %1; cvt.u32.u64 %0, t; }" : "=r"(a) : "l"(p));
    return a;
}
#define SW128(o) ((o) ^ (((o) >> 3) & 0x70))

#define CP16(dst, src) \
    asm volatile("cp.async.cg.shared.global [%0], [%1], 16;" :: "r"(dst), "l"(src) : "memory")
#define CP_COMMIT() asm volatile("cp.async.commit_group;" ::: "memory")
#define CP_WAIT2()  asm volatile("cp.async.wait_group 2;" ::: "memory")
#define CP_WAIT1()  asm volatile("cp.async.wait_group 1;" ::: "memory")
#define CP_WAIT0()  asm volatile("cp.async.wait_group 0;" ::: "memory")

#define LDSM4(r0, r1, r2, r3, addr) \
    asm volatile("ldmatrix.sync.aligned.m8n8.x4.shared.b16 {%0,%1,%2,%3}, [%4];" \
                 : "=r"(r0), "=r"(r1), "=r"(r2), "=r"(r3) : "r"(addr))

#define MMA_F16(c, a, b) \
    asm volatile("mma.sync.aligned.m16n8k16.row.col.f32.f16.f16.f32 " \
                 "{%0,%1,%2,%3}, {%4,%5,%6,%7}, {%8,%9}, {%0,%1,%2,%3};" \
                 : "+f"((c)[0]), "+f"((c)[1]), "+f"((c)[2]), "+f"((c)[3]) \
                 : "r"((a)[0]), "r"((a)[1]), "r"((a)[2]), "r"((a)[3]), \
                   "r"((b)[0]), "r"((b)[1]))

// split fp32 pair -> hi f16x2 + lo f16x2 (residual)
__device__ __forceinline__ void split2h(float x, float y, uint32_t& h, uint32_t& l) {
    asm("cvt.rn.f16x2.f32 %0, %1, %2;" : "=r"(h) : "f"(y), "f"(x));
    __half2 hh = *reinterpret_cast<__half2*>(&h);
    float hx = __low2float(hh), hy = __high2float(hh);
    asm("cvt.rn.f16x2.f32 %0, %1, %2;" : "=r"(l) : "f"(y - hy), "f"(x - hx));
}

// ---------------- merged weight conversion (ONE launch) ---------------------
// W[K][N] fp32 -> Wt[N][K] fp16 (transposed). Tile 32x32 per block.
// groups: 0..3 q/k/v/p (12288 tiles each), 4 f1 (49152), 5 f2 (49152), 6 head (512)
__global__ __launch_bounds__(256)
void convAll(const float* __restrict__ Wq, const float* __restrict__ Wk,
             const float* __restrict__ Wv, const float* __restrict__ Wp,
             const float* __restrict__ W1, const float* __restrict__ W2,
             const float* __restrict__ Wh,
             __half* oq, __half* ok, __half* ov, __half* op,
             __half* o1, __half* o2, __half* oh)
{
    int b = blockIdx.x;
    const float* W; __half* O; int K, N;
    if (b < 49152) {
        int g = b / 12288; b -= g * 12288; K = Eq; N = Eq;
        W = (g==0) ? Wq : (g==1) ? Wk : (g==2) ? Wv : Wp;
        O = (g==0) ? oq : (g==1) ? ok : (g==2) ? ov : op;
    } else if (b < 98304)  { b -= 49152; K = Eq; N = Fq; W = W1; O = o1; }
    else if (b < 147456)   { b -= 98304; K = Fq; N = Eq; W = W2; O = o2; }
    else                   { b -= 147456; K = Eq; N = Vq; W = Wh; O = oh; }

    int tilesN = N >> 5;
    int per = tilesN * (K >> 5);
    int l = b / per; int rem = b - l * per;
    int kt = rem / tilesN, nt = rem - kt * tilesN;
    const float* Wl = W + (size_t)l * K * N;
    __half* Ol = O + (size_t)l * K * N;
    int k0 = kt * 32, n0 = nt * 32;

    __shared__ float t[32][33];
    int tid = threadIdx.x;
    int r = tid >> 5, c = tid & 31;
    #pragma unroll
    for (int i = 0; i < 4; i++)
        t[r + 8*i][c] = Wl[(size_t)(k0 + r + 8*i) * N + n0 + c];
    __syncthreads();
    #pragma unroll
    for (int i = 0; i < 4; i++)
        Ol[(size_t)(n0 + r + 8*i) * K + k0 + c] = __float2half(t[c][r + 8*i]);
}

// ---------------- embedding -------------------------------------------------
__global__ void embed_kernel(const int* __restrict__ x,
                             const float* __restrict__ tok,
                             const float* __restrict__ pos,
                             float* __restrict__ out)
{
    int row = blockIdx.x;
    int t   = row & (Tq-1);
    int id  = x[row];
    int tid = threadIdx.x;
    float4 a = ((const float4*)(tok + (size_t)id*Eq))[tid];
    float4 p = ((const float4*)(pos + (size_t)t*Eq))[tid];
    float4 o; o.x=a.x+p.x; o.y=a.y+p.y; o.z=a.z+p.z; o.w=a.w+p.w;
    ((float4*)(out + (size_t)row*Eq))[tid] = o;
}

// ---------------- layernorm (writes fp16 hi/lo) -----------------------------
__global__ void ln_kernel(const float* __restrict__ x,
                          const float* __restrict__ g,
                          const float* __restrict__ b,
                          __half* __restrict__ ohi,
                          __half* __restrict__ olo)
{
    int row = blockIdx.x;
    int tid = threadIdx.x;
    const float4* xr = (const float4*)(x + (size_t)row*Eq);
    float4 xv = xr[tid];
    float s  = xv.x + xv.y + xv.z + xv.w;
    float sq = xv.x*xv.x + xv.y*xv.y + xv.z*xv.z + xv.w*xv.w;
    #pragma unroll
    for (int off = 16; off > 0; off >>= 1) {
        s  += __shfl_xor_sync(0xffffffffu, s,  off);
        sq += __shfl_xor_sync(0xffffffffu, sq, off);
    }
    __shared__ float r1[8], r2[8];
    int w = tid >> 5;
    if ((tid & 31) == 0) { r1[w] = s; r2[w] = sq; }
    __syncthreads();
    float ts = 0.f, tq = 0.f;
    #pragma unroll
    for (int i = 0; i < 8; i++) { ts += r1[i]; tq += r2[i]; }
    float mean = ts * (1.0f/Eq);
    float var  = tq * (1.0f/Eq) - mean*mean;
    float rstd = rsqrtf(var + 1e-5f);
    float4 gv = ((const float4*)g)[tid];
    float4 bv = ((const float4*)b)[tid];
    float4 ov;
    ov.x = (xv.x-mean)*rstd*gv.x + bv.x;
    ov.y = (xv.y-mean)*rstd*gv.y + bv.y;
    ov.z = (xv.z-mean)*rstd*gv.z + bv.z;
    ov.w = (xv.w-mean)*rstd*gv.w + bv.w;
    uint32_t h0,h1,l0,l1;
    split2h(ov.x, ov.y, h0, l0);
    split2h(ov.z, ov.w, h1, l1);
    uint2 hv; hv.x = h0; hv.y = h1;
    uint2 lv; lv.x = l0; lv.y = l1;
    ((uint2*)(ohi + (size_t)row*Eq))[tid] = hv;
    ((uint2*)(olo + (size_t)row*Eq))[tid] = lv;
}

// ================ HMMA fp16 GEMM (cp.async, 4-stage, 1 sync/chunk) ==========
// C[M,N] = A[M,K] @ B^T (B stored [N][K] fp16). A = Ah + Al (fp16 2-term).
// CTA 128x128, K chunk 64, 8 warps, warp tile 32x64, 2 MMA terms.
// SMEM per stage: Ah,Al,Bh each [128][64] fp16 SW128 = 3x16KB = 48KB; 4 stages.
#define ST_STRIDE 49152u
#define GT_SMEM (4*49152)

__device__ __forceinline__ float gelu_exact(float v) {
    return 0.5f * v * (1.0f + erff(v * 0.7071067811865475f));
}

__device__ __forceinline__ void load_stage(
    uint32_t sb, const __half* __restrict__ Ah, const __half* __restrict__ Al,
    const __half* __restrict__ Bh, const uint32_t* soff,
    size_t aBase, size_t bBase, int K)
{
    #pragma unroll
    for (int c = 0; c < 4; c++) {
        size_t ao = aBase + (size_t)(32*c) * K;
        size_t bo = bBase + (size_t)(32*c) * K;
        CP16(sb + soff[c],          Ah + ao);
        CP16(sb + 16384u + soff[c], Al + ao);
        CP16(sb + 32768u + soff[c], Bh + bo);
    }
    CP_COMMIT();
}

__global__ __launch_bounds__(256)
void gemm_hf(const __half* __restrict__ Ah, const __half* __restrict__ Al,
             const __half* __restrict__ Bh,
             const float* __restrict__ bias, const float* __restrict__ res,
             float* __restrict__ C, __half* __restrict__ Chi,
             __half* __restrict__ Clo, int M, int N, int K, int act)
{
    extern __shared__ char smem[];
    const uint32_t sbase = smem_u32(smem);
    const int tid  = threadIdx.x;
    const int wid  = tid >> 5;
    const int lane = tid & 31;
    const int bm = blockIdx.y * 128;
    const int bn = blockIdx.x * 128;

    // cp.async loader mapping: 4 rows/thread per tile
    uint32_t soff[4];
    #pragma unroll
    for (int c = 0; c < 4; c++)
        soff[c] = SW128((uint32_t)((32*c + (tid >> 3))*128 + (tid & 7)*16));
    const size_t aBase0 = (size_t)(bm + (tid >> 3)) * K + (tid & 7)*8;
    const size_t bBase0 = (size_t)(bn + (tid >> 3)) * K + (tid & 7)*8;

    // warp tile mapping
    const int m0 = (wid & 3) * 32;
    const int n0 = (wid >> 2) * 64;
    uint32_t aRow[2], aMask[2];
    #pragma unroll
    for (int mt = 0; mt < 2; mt++) {
        int r = m0 + mt*16 + (lane & 15);
        aRow[mt]  = (uint32_t)r * 128u;
        aMask[mt] = (uint32_t)(r & 7) << 4;
    }
    const uint32_t kA = ((uint32_t)(lane >> 4)) << 4;
    uint32_t bRow[4], bMask[4];
    #pragma unroll
    for (int p = 0; p < 4; p++) {
        int r = n0 + p*16 + (((lane >> 4) & 1) << 3) + (lane & 7);
        bRow[p]  = (uint32_t)r * 128u;
        bMask[p] = (uint32_t)(r & 7) << 4;
    }
    const uint32_t kB = ((uint32_t)(lane & 8)) << 1;

    float acc[2][8][4];
    #pragma unroll
    for (int mt = 0; mt < 2; mt++)
        #pragma unroll
        for (int nt = 0; nt < 8; nt++)
            #pragma unroll
            for (int c = 0; c < 4; c++) acc[mt][nt][c] = 0.f;

    const int nst = K >> 6;

    // prologue: stages 0..2
    #pragma unroll
    for (int i = 0; i < 3; i++)
        if (i < nst)
            load_stage(sbase + (uint32_t)i*ST_STRIDE, Ah, Al, Bh, soff,
                       aBase0 + (size_t)i*64, bBase0 + (size_t)i*64, K);

    for (int s = 0; s < nst; s++) {
        int rem = nst - 1 - s;
        if (rem >= 2) CP_WAIT2(); else if (rem == 1) CP_WAIT1(); else CP_WAIT0();
        __syncthreads();
        if (s + 3 < nst)
            load_stage(sbase + (uint32_t)((s + 3) & 3)*ST_STRIDE, Ah, Al, Bh, soff,
                       aBase0 + (size_t)(s + 3)*64, bBase0 + (size_t)(s + 3)*64, K);
        // compute chunk s from buffer s&3
        {
            const uint32_t tb = sbase + (uint32_t)(s & 3)*ST_STRIDE;
            const uint32_t bufAh = tb, bufAl = tb + 16384u, bufBh = tb + 32768u;
            #pragma unroll
            for (int ks = 0; ks < 4; ks++) {
                uint32_t ah[2][4], al[2][4];
                #pragma unroll
                for (int mt = 0; mt < 2; mt++) {
                    uint32_t co  = (uint32_t)(ks*32) + kA;
                    uint32_t off = aRow[mt] + (co ^ aMask[mt]);
                    LDSM4(ah[mt][0], ah[mt][1], ah[mt][2], ah[mt][3], bufAh + off);
                    LDSM4(al[mt][0], al[mt][1], al[mt][2], al[mt][3], bufAl + off);
                }
                uint32_t bh[8][2];
                #pragma unroll
                for (int p = 0; p < 4; p++) {
                    uint32_t co  = (uint32_t)(ks*32) + kB;
                    uint32_t off = bRow[p] + (co ^ bMask[p]);
                    uint32_t t0,t1,t2,t3;
                    LDSM4(t0, t1, t2, t3, bufBh + off);
                    bh[2*p][0]=t0; bh[2*p][1]=t1; bh[2*p+1][0]=t2; bh[2*p+1][1]=t3;
                }
                #pragma unroll
                for (int mt = 0; mt < 2; mt++)
                    #pragma unroll
                    for (int nt = 0; nt < 8; nt++) {
                        MMA_F16(acc[mt][nt], ah[mt], bh[nt]);
                        MMA_F16(acc[mt][nt], al[mt], bh[nt]);
                    }
            }
        }
    }

    // ---- epilogue ----
    #pragma unroll
    for (int mt = 0; mt < 2; mt++) {
        #pragma unroll
        for (int nt = 0; nt < 8; nt++) {
            int mrow = bm + m0 + mt*16 + (lane >> 2);
            int ncol = bn + n0 + nt*8 + ((lane & 3) << 1);
            #pragma unroll
            for (int half = 0; half < 2; half++) {
                int m = mrow + half*8;
                float v0 = acc[mt][nt][half*2 + 0];
                float v1 = acc[mt][nt][half*2 + 1];
                if (bias) { v0 += bias[ncol]; v1 += bias[ncol + 1]; }
                if (act)  { v0 = gelu_exact(v0); v1 = gelu_exact(v1); }
                if (res) {
                    const float2 rr = *(const float2*)(res + (size_t)m * N + ncol);
                    v0 += rr.x; v1 += rr.y;
                }
                if (C) {
                    float2 o; o.x = v0; o.y = v1;
                    *(float2*)(C + (size_t)m * N + ncol) = o;
                }
                if (Chi) {
                    uint32_t hh, ll;
                    split2h(v0, v1, hh, ll);
                    *(uint32_t*)(Chi + (size_t)m * N + ncol) = hh;
                    *(uint32_t*)(Clo + (size_t)m * N + ncol) = ll;
                }
            }
        }
    }
}

// ---------------- attention: scores + softmax -------------------------------
#define TQA 16
__global__ __launch_bounds__(128)
void attn_scores(const float* __restrict__ q, const float* __restrict__ k,
                 float* __restrict__ att)
{
    int tile = blockIdx.x & 31;
    int bh   = blockIdx.x >> 5;
    int hh   = bh & (Hq-1);
    int bb   = bh >> 4;
    int t0   = tile * TQA;
    int tid  = threadIdx.x;

    __shared__ float qs[TQA][Dq];
    __shared__ float sm[TQA][Tq];
    __shared__ float red[4];

    for (int i = tid; i < TQA*Dq; i += 128) {
        int r = i >> 6, d = i & 63;
        qs[r][d] = q[(((size_t)bb*Tq + t0 + r)*Hq + hh)*Dq + d];
    }
    __syncthreads();

    int tmax = t0 + TQA - 1;
    for (int kk = tid; kk < Tq; kk += 128) {
        if (kk <= tmax) {
            const float4* krow = (const float4*)(k + (((size_t)bb*Tq + kk)*Hq + hh)*Dq);
            float4 kr[16];
            #pragma unroll
            for (int j = 0; j < 16; j++) kr[j] = krow[j];
            #pragma unroll
            for (int r = 0; r < TQA; r++) {
                const float4* qr = (const float4*)qs[r];
                float dot = 0.f;
                #pragma unroll
                for (int j = 0; j < 16; j++) {
                    float4 qv = qr[j];
                    dot += qv.x*kr[j].x + qv.y*kr[j].y + qv.z*kr[j].z + qv.w*kr[j].w;
                }
                sm[r][kk] = (kk <= t0 + r) ? dot * 0.125f : -INFINITY;
            }
        } else {
            #pragma unroll
            for (int r = 0; r < TQA; r++) sm[r][kk] = -INFINITY;
        }
    }
    __syncthreads();

    int lane = tid & 31, w = tid >> 5;
    for (int r = 0; r < TQA; r++) {
        float mx = -INFINITY;
        for (int kk = tid; kk < Tq; kk += 128) mx = fmaxf(mx, sm[r][kk]);
        #pragma unroll
        for (int off = 16; off > 0; off >>= 1)
            mx = fmaxf(mx, __shfl_xor_sync(0xffffffffu, mx, off));
        if (lane == 0) red[w] = mx;
        __syncthreads();
        mx = fmaxf(fmaxf(red[0], red[1]), fmaxf(red[2], red[3]));
        __syncthreads();
        float s = 0.f;
        for (int kk = tid; kk < Tq; kk += 128) {
            float e = expf(sm[r][kk] - mx);
            sm[r][kk] = e;
            s += e;
        }
        #pragma unroll
        for (int off = 16; off > 0; off >>= 1)
            s += __shfl_xor_sync(0xffffffffu, s, off);
        if (lane == 0) red[w] = s;
        __syncthreads();
        s = red[0] + red[1] + red[2] + red[3];
        __syncthreads();
        float inv = 1.0f / s;
        float* arow = att + ((size_t)bh*Tq + (t0 + r)) * Tq;
        for (int kk = tid; kk < Tq; kk += 128) arow[kk] = sm[r][kk] * inv;
    }
}

// ---------------- attention: O = att @ V (writes y hi/lo fp16) --------------
__global__ __launch_bounds__(128)
void attn_out(const float* __restrict__ att, const float* __restrict__ v,
              __half* __restrict__ yhi, __half* __restrict__ ylo)
{
    int tile = blockIdx.x & 31;
    int bh   = blockIdx.x >> 5;
    int hh   = bh & (Hq-1);
    int bb   = bh >> 4;
    int t0   = tile * TQA;
    int tid  = threadIdx.x;

    __shared__ float at[Tq][20];
    __shared__ float part[TQA][Dq];

    for (int i = tid; i < TQA*Tq; i += 128) {
        int r = i >> 9, kk = i & 511;
        at[kk][r] = att[((size_t)bh*Tq + t0 + r)*Tq + kk];
    }
    __syncthreads();

    int half = tid >> 6;
    int d    = tid & 63;
    float acc[TQA];
    #pragma unroll
    for (int r = 0; r < TQA; r++) acc[r] = 0.f;

    int kmax = t0 + TQA;
    for (int kk = half; kk < kmax; kk += 2) {
        float vv = v[(((size_t)bb*Tq + kk)*Hq + hh)*Dq + d];
        const float4* ar = (const float4*)at[kk];
        #pragma unroll
        for (int j = 0; j < 4; j++) {
            float4 a4 = ar[j];
            acc[j*4+0] += a4.x * vv;
            acc[j*4+1] += a4.y * vv;
            acc[j*4+2] += a4.z * vv;
            acc[j*4+3] += a4.w * vv;
        }
    }
    if (half == 1) {
        #pragma unroll
        for (int r = 0; r < TQA; r++) part[r][d] = acc[r];
    }
    __syncthreads();
    if (half == 0) {
        #pragma unroll
        for (int r = 0; r < TQA; r++) {
            float o = acc[r] + part[r][d];
            size_t idx = (((size_t)bb*Tq + t0 + r)*Hq + hh)*Dq + d;
            __half hv = __float2half(o);
            yhi[idx] = hv;
            ylo[idx] = __float2half(o - __half2float(hv));
        }
    }
}

// ---------------- host orchestration ----------------------------------------
extern "C" void kernel_launch(void* const* d_in, const int* in_sizes, int n_in,
                              void* d_out, int out_size)
{
    const int*   x      = (const int*)  d_in[0];
    const float* tok    = (const float*)d_in[2];
    const float* pos    = (const float*)d_in[3];
    const float* ln1g   = (const float*)d_in[4];
    const float* ln1b   = (const float*)d_in[5];
    const float* Wqp    = (const float*)d_in[6];
    const float* bqp    = (const float*)d_in[7];
    const float* Wkp    = (const float*)d_in[8];
    const float* bkp    = (const float*)d_in[9];
    const float* Wvp    = (const float*)d_in[10];
    const float* bvp    = (const float*)d_in[11];
    const float* Wpp    = (const float*)d_in[12];
    const float* bpp    = (const float*)d_in[13];
    const float* ln2g   = (const float*)d_in[14];
    const float* ln2b   = (const float*)d_in[15];
    const float* Wf1p   = (const float*)d_in[16];
    const float* bf1p   = (const float*)d_in[17];
    const float* Wf2p   = (const float*)d_in[18];
    const float* bf2p   = (const float*)d_in[19];
    const float* lnfg   = (const float*)d_in[20];
    const float* lnfb   = (const float*)d_in[21];
    const float* headw  = (const float*)d_in[22];

    float *h, *q, *k, *v, *att;
    cudaGetSymbolAddress((void**)&h,   g_h);
    cudaGetSymbolAddress((void**)&q,   g_q);
    cudaGetSymbolAddress((void**)&k,   g_k);
    cudaGetSymbolAddress((void**)&v,   g_v);
    cudaGetSymbolAddress((void**)&att, g_att);

    __half *xnh,*xnl,*yh,*yl,*mlh,*mll;
    cudaGetSymbolAddress((void**)&xnh, g_xn_hi);
    cudaGetSymbolAddress((void**)&xnl, g_xn_lo);
    cudaGetSymbolAddress((void**)&yh,  g_y_hi);
    cudaGetSymbolAddress((void**)&yl,  g_y_lo);
    cudaGetSymbolAddress((void**)&mlh, g_ml_hi);
    cudaGetSymbolAddress((void**)&mll, g_ml_lo);

    __half *wq,*wk,*wv,*wp,*w1,*w2,*wh;
    cudaGetSymbolAddress((void**)&wq, g_wq);
    cudaGetSymbolAddress((void**)&wk, g_wk);
    cudaGetSymbolAddress((void**)&wv, g_wv);
    cudaGetSymbolAddress((void**)&wp, g_wp);
    cudaGetSymbolAddress((void**)&w1, g_w1);
    cudaGetSymbolAddress((void**)&w2, g_w2);
    cudaGetSymbolAddress((void**)&wh, g_wh);

    cudaFuncSetAttribute(gemm_hf, cudaFuncAttributeMaxDynamicSharedMemorySize, GT_SMEM);

    // launch 1: merged weight conversion (keeps GEMM at profile slot 6)
    convAll<<<147968, 256>>>(Wqp, Wkp, Wvp, Wpp, Wf1p, Wf2p, headw,
                             wq, wk, wv, wp, w1, w2, wh);
    // launch 2
    embed_kernel<<<Mq, 256>>>(x, tok, pos, h);

    dim3 gEE(Eq/128, Mq/128);     // (8, 32)
    dim3 gEF(Fq/128, Mq/128);     // (32, 32)
    dim3 gEV(Vq/128, Mq/128);     // (4, 32)

    for (int l = 0; l < Lq; l++) {
        const size_t oE = (size_t)l*Eq*Eq;
        const size_t oF = (size_t)l*Eq*Fq;

        // launches 3,4,5,6 in layer 0 -> slot 6 = gemm_hf (V projection)
        ln_kernel<<<Mq, 256>>>(h, ln1g + l*Eq, ln1b + l*Eq, xnh, xnl);
        gemm_hf<<<gEE, 256, GT_SMEM>>>(xnh, xnl, wq+oE, bqp + l*Eq, nullptr,
                                       q, nullptr, nullptr, Mq, Eq, Eq, 0);
        gemm_hf<<<gEE, 256, GT_SMEM>>>(xnh, xnl, wk+oE, bkp + l*Eq, nullptr,
                                       k, nullptr, nullptr, Mq, Eq, Eq, 0);
        gemm_hf<<<gEE, 256, GT_SMEM>>>(xnh, xnl, wv+oE, bvp + l*Eq, nullptr,
                                       v, nullptr, nullptr, Mq, Eq, Eq, 0);

        attn_scores<<<Bq*Hq*(Tq/TQA), 128>>>(q, k, att);
        attn_out   <<<Bq*Hq*(Tq/TQA), 128>>>(att, v, yh, yl);

        gemm_hf<<<gEE, 256, GT_SMEM>>>(yh, yl, wp+oE, bpp + l*Eq, h,
                                       h, nullptr, nullptr, Mq, Eq, Eq, 0);

        ln_kernel<<<Mq, 256>>>(h, ln2g + l*Eq, ln2b + l*Eq, xnh, xnl);
        gemm_hf<<<gEF, 256, GT_SMEM>>>(xnh, xnl, w1+oF, bf1p + l*Fq, nullptr,
                                       nullptr, mlh, mll, Mq, Fq, Eq, 1);
        gemm_hf<<<gEE, 256, GT_SMEM>>>(mlh, mll, w2+oF, bf2p + l*Eq, h,
                                       h, nullptr, nullptr, Mq, Eq, Fq, 0);
    }

    ln_kernel<<<Mq, 256>>>(h, lnfg, lnfb, xnh, xnl);
    gemm_hf<<<gEV, 256, GT_SMEM>>>(xnh, xnl, wh, nullptr, nullptr,
                                   (float*)d_out, nullptr, nullptr, Mq, Vq, Eq, 0);
}

// round 7
// speedup vs baseline: 1.6865x; 1.6865x over previous
#include <cuda_runtime.h>
#include <cuda_fp16.h>
#include <math.h>
#include <stdint.h>

#define Lq 12
#define Eq 1024
#define Hq 16
#define Tq 512
#define Bq 8
#define Vq 512
#define Fq 4096
#define Dq 64
#define Mq (Bq*Tq)

// ---------------- scratch ----------------------------------------------------
__device__ float g_h[Mq*Eq];
__device__ __half g_xn_hi[Mq*Eq],  g_xn_lo[Mq*Eq];
__device__ __half g_q_hi [Mq*Eq],  g_q_lo [Mq*Eq];
__device__ __half g_k_hi [Mq*Eq],  g_k_lo [Mq*Eq];
__device__ __half g_v_hi [Mq*Eq],  g_v_lo [Mq*Eq];
__device__ __half g_y_hi [Mq*Eq],  g_y_lo [Mq*Eq];
__device__ __half g_ml_hi[(size_t)Mq*Fq], g_ml_lo[(size_t)Mq*Fq];
__device__ __half g_wq[(size_t)Lq*Eq*Eq];
__device__ __half g_wk[(size_t)Lq*Eq*Eq];
__device__ __half g_wv[(size_t)Lq*Eq*Eq];
__device__ __half g_wp[(size_t)Lq*Eq*Eq];
__device__ __half g_w1[(size_t)Lq*Eq*Fq];
__device__ __half g_w2[(size_t)Lq*Fq*Eq];
__device__ __half g_wh[(size_t)Eq*Vq];

// ---------------- helpers ----------------------------------------------------
__device__ __forceinline__ uint32_t smem_u32(const void* p) {
    uint32_t a;
    asm("{ .reg .u64 t; cvta.to.shared.u64 t, %1; cvt.u32.u64 %0, t; }" : "=r"(a) : "l"(p));
    return a;
}
#define SW128(o) ((o) ^ (((o) >> 3) & 0x70))
#define CP16(dst, src) \
    asm volatile("cp.async.cg.shared.global [%0], [%1], 16;" :: "r"(dst), "l"(src) : "memory")
#define CP_COMMIT() asm volatile("cp.async.commit_group;" ::: "memory")
#define CP_WAIT1()  asm volatile("cp.async.wait_group 1;" ::: "memory")
#define CP_WAIT0()  asm volatile("cp.async.wait_group 0;" ::: "memory")
#define LDSM4(r0, r1, r2, r3, addr) \
    asm volatile("ldmatrix.sync.aligned.m8n8.x4.shared.b16 {%0,%1,%2,%3}, [%4];" \
                 : "=r"(r0), "=r"(r1), "=r"(r2), "=r"(r3) : "r"(addr))
#define LDSM4T(r0, r1, r2, r3, addr) \
    asm volatile("ldmatrix.sync.aligned.m8n8.x4.trans.shared.b16 {%0,%1,%2,%3}, [%4];" \
                 : "=r"(r0), "=r"(r1), "=r"(r2), "=r"(r3) : "r"(addr))
#define MMA_F16(c, a, b) \
    asm volatile("mma.sync.aligned.m16n8k16.row.col.f32.f16.f16.f32 " \
                 "{%0,%1,%2,%3}, {%4,%5,%6,%7}, {%8,%9}, {%0,%1,%2,%3};" \
                 : "+f"((c)[0]), "+f"((c)[1]), "+f"((c)[2]), "+f"((c)[3]) \
                 : "r"((a)[0]), "r"((a)[1]), "r"((a)[2]), "r"((a)[3]), \
                   "r"((b)[0]), "r"((b)[1]))
#define MMA_F16B(c, a, b0, b1) \
    asm volatile("mma.sync.aligned.m16n8k16.row.col.f32.f16.f16.f32 " \
                 "{%0,%1,%2,%3}, {%4,%5,%6,%7}, {%8,%9}, {%0,%1,%2,%3};" \
                 : "+f"((c)[0]), "+f"((c)[1]), "+f"((c)[2]), "+f"((c)[3]) \
                 : "r"((a)[0]), "r"((a)[1]), "r"((a)[2]), "r"((a)[3]), \
                   "r"(b0), "r"(b1))

__device__ __forceinline__ void split2h(float x, float y, uint32_t& h, uint32_t& l) {
    asm("cvt.rn.f16x2.f32 %0, %1, %2;" : "=r"(h) : "f"(y), "f"(x));
    __half2 hh = *reinterpret_cast<__half2*>(&h);
    float hx = __low2float(hh), hy = __high2float(hh);
    asm("cvt.rn.f16x2.f32 %0, %1, %2;" : "=r"(l) : "f"(y - hy), "f"(x - hx));
}

// ---------------- merged weight conversion -----------------------------------
__global__ __launch_bounds__(256)
void convAll(const float* __restrict__ Wq, const float* __restrict__ Wk,
             const float* __restrict__ Wv, const float* __restrict__ Wp,
             const float* __restrict__ W1, const float* __restrict__ W2,
             const float* __restrict__ Wh,
             __half* oq, __half* ok, __half* ov, __half* op,
             __half* o1, __half* o2, __half* oh)
{
    int b = blockIdx.x;
    const float* W; __half* O; int K, N;
    if (b < 49152) {
        int g = b / 12288; b -= g * 12288; K = Eq; N = Eq;
        W = (g==0) ? Wq : (g==1) ? Wk : (g==2) ? Wv : Wp;
        O = (g==0) ? oq : (g==1) ? ok : (g==2) ? ov : op;
    } else if (b < 98304)  { b -= 49152; K = Eq; N = Fq; W = W1; O = o1; }
    else if (b < 147456)   { b -= 98304; K = Fq; N = Eq; W = W2; O = o2; }
    else                   { b -= 147456; K = Eq; N = Vq; W = Wh; O = oh; }
    int tilesN = N >> 5;
    int per = tilesN * (K >> 5);
    int l = b / per; int rem = b - l * per;
    int kt = rem / tilesN, nt = rem - kt * tilesN;
    const float* Wl = W + (size_t)l * K * N;
    __half* Ol = O + (size_t)l * K * N;
    int k0 = kt * 32, n0 = nt * 32;
    __shared__ float t[32][33];
    int tid = threadIdx.x;
    int r = tid >> 5, c = tid & 31;
    #pragma unroll
    for (int i = 0; i < 4; i++)
        t[r + 8*i][c] = Wl[(size_t)(k0 + r + 8*i) * N + n0 + c];
    __syncthreads();
    #pragma unroll
    for (int i = 0; i < 4; i++)
        Ol[(size_t)(n0 + r + 8*i) * K + k0 + c] = __float2half(t[c][r + 8*i]);
}

// ---------------- embedding ---------------------------------------------------
__global__ void embed_kernel(const int* __restrict__ x,
                             const float* __restrict__ tok,
                             const float* __restrict__ pos,
                             float* __restrict__ out)
{
    int row = blockIdx.x;
    int t   = row & (Tq-1);
    int id  = x[row];
    int tid = threadIdx.x;
    float4 a = ((const float4*)(tok + (size_t)id*Eq))[tid];
    float4 p = ((const float4*)(pos + (size_t)t*Eq))[tid];
    float4 o; o.x=a.x+p.x; o.y=a.y+p.y; o.z=a.z+p.z; o.w=a.w+p.w;
    ((float4*)(out + (size_t)row*Eq))[tid] = o;
}

// ---------------- layernorm ---------------------------------------------------
__global__ void ln_kernel(const float* __restrict__ x,
                          const float* __restrict__ g,
                          const float* __restrict__ b,
                          __half* __restrict__ ohi,
                          __half* __restrict__ olo)
{
    int row = blockIdx.x;
    int tid = threadIdx.x;
    const float4* xr = (const float4*)(x + (size_t)row*Eq);
    float4 xv = xr[tid];
    float s  = xv.x + xv.y + xv.z + xv.w;
    float sq = xv.x*xv.x + xv.y*xv.y + xv.z*xv.z + xv.w*xv.w;
    #pragma unroll
    for (int off = 16; off > 0; off >>= 1) {
        s  += __shfl_xor_sync(0xffffffffu, s,  off);
        sq += __shfl_xor_sync(0xffffffffu, sq, off);
    }
    __shared__ float r1[8], r2[8];
    int w = tid >> 5;
    if ((tid & 31) == 0) { r1[w] = s; r2[w] = sq; }
    __syncthreads();
    float ts = 0.f, tq = 0.f;
    #pragma unroll
    for (int i = 0; i < 8; i++) { ts += r1[i]; tq += r2[i]; }
    float mean = ts * (1.0f/Eq);
    float var  = tq * (1.0f/Eq) - mean*mean;
    float rstd = rsqrtf(var + 1e-5f);
    float4 gv = ((const float4*)g)[tid];
    float4 bv = ((const float4*)b)[tid];
    float4 ov;
    ov.x = (xv.x-mean)*rstd*gv.x + bv.x;
    ov.y = (xv.y-mean)*rstd*gv.y + bv.y;
    ov.z = (xv.z-mean)*rstd*gv.z + bv.z;
    ov.w = (xv.w-mean)*rstd*gv.w + bv.w;
    uint32_t h0,h1,l0,l1;
    split2h(ov.x, ov.y, h0, l0);
    split2h(ov.z, ov.w, h1, l1);
    uint2 hv; hv.x = h0; hv.y = h1;
    uint2 lv; lv.x = l0; lv.y = l1;
    ((uint2*)(ohi + (size_t)row*Eq))[tid] = hv;
    ((uint2*)(olo + (size_t)row*Eq))[tid] = lv;
}

// ================ HMMA fp16 GEMM (2-stage, 2 CTAs/SM) =======================
#define ST_STRIDE 49152u
#define GT_SMEM (2*49152)

__device__ __forceinline__ float gelu_exact(float v) {
    return 0.5f * v * (1.0f + erff(v * 0.7071067811865475f));
}

__device__ __forceinline__ void load_stage(
    uint32_t sb, const __half* __restrict__ Ah, const __half* __restrict__ Al,
    const __half* __restrict__ Bh, const uint32_t* soff,
    size_t aBase, size_t bBase, int K)
{
    #pragma unroll
    for (int c = 0; c < 4; c++) {
        size_t ao = aBase + (size_t)(32*c) * K;
        size_t bo = bBase + (size_t)(32*c) * K;
        CP16(sb + soff[c],          Ah + ao);
        CP16(sb + 16384u + soff[c], Al + ao);
        CP16(sb + 32768u + soff[c], Bh + bo);
    }
    CP_COMMIT();
}

__global__ __launch_bounds__(256, 2)
void gemm_hf(const __half* __restrict__ Ah, const __half* __restrict__ Al,
             const __half* __restrict__ Bh,
             const float* __restrict__ bias, const float* __restrict__ res,
             float* __restrict__ C, __half* __restrict__ Chi,
             __half* __restrict__ Clo, int M, int N, int K, int act)
{
    extern __shared__ char smem[];
    const uint32_t sbase = smem_u32(smem);
    const int tid  = threadIdx.x;
    const int wid  = tid >> 5;
    const int lane = tid & 31;
    const int bm = blockIdx.y * 128;
    const int bn = blockIdx.x * 128;

    uint32_t soff[4];
    #pragma unroll
    for (int c = 0; c < 4; c++)
        soff[c] = SW128((uint32_t)((32*c + (tid >> 3))*128 + (tid & 7)*16));
    const size_t aBase0 = (size_t)(bm + (tid >> 3)) * K + (tid & 7)*8;
    const size_t bBase0 = (size_t)(bn + (tid >> 3)) * K + (tid & 7)*8;

    const int m0 = (wid & 3) * 32;
    const int n0 = (wid >> 2) * 64;
    uint32_t aRow[2], aMask[2];
    #pragma unroll
    for (int mt = 0; mt < 2; mt++) {
        int r = m0 + mt*16 + (lane & 15);
        aRow[mt]  = (uint32_t)r * 128u;
        aMask[mt] = (uint32_t)(r & 7) << 4;
    }
    const uint32_t kA = ((uint32_t)(lane >> 4)) << 4;
    uint32_t bRow[4], bMask[4];
    #pragma unroll
    for (int p = 0; p < 4; p++) {
        int r = n0 + p*16 + (((lane >> 4) & 1) << 3) + (lane & 7);
        bRow[p]  = (uint32_t)r * 128u;
        bMask[p] = (uint32_t)(r & 7) << 4;
    }
    const uint32_t kB = ((uint32_t)(lane & 8)) << 1;

    float acc[2][8][4];
    #pragma unroll
    for (int mt = 0; mt < 2; mt++)
        #pragma unroll
        for (int nt = 0; nt < 8; nt++)
            #pragma unroll
            for (int c = 0; c < 4; c++) acc[mt][nt][c] = 0.f;

    const int nst = K >> 6;
    load_stage(sbase, Ah, Al, Bh, soff, aBase0, bBase0, K);
    if (nst > 1)
        load_stage(sbase + ST_STRIDE, Ah, Al, Bh, soff, aBase0 + 64, bBase0 + 64, K);

    for (int s = 0; s < nst; s++) {
        if (s + 1 < nst) CP_WAIT1(); else CP_WAIT0();
        __syncthreads();
        {
            const uint32_t tb = sbase + (uint32_t)(s & 1)*ST_STRIDE;
            const uint32_t bufAh = tb, bufAl = tb + 16384u, bufBh = tb + 32768u;
            #pragma unroll
            for (int ks = 0; ks < 4; ks++) {
                uint32_t ah[2][4], al[2][4];
                #pragma unroll
                for (int mt = 0; mt < 2; mt++) {
                    uint32_t co  = (uint32_t)(ks*32) + kA;
                    uint32_t off = aRow[mt] + (co ^ aMask[mt]);
                    LDSM4(ah[mt][0], ah[mt][1], ah[mt][2], ah[mt][3], bufAh + off);
                    LDSM4(al[mt][0], al[mt][1], al[mt][2], al[mt][3], bufAl + off);
                }
                uint32_t bh[8][2];
                #pragma unroll
                for (int p = 0; p < 4; p++) {
                    uint32_t co  = (uint32_t)(ks*32) + kB;
                    uint32_t off = bRow[p] + (co ^ bMask[p]);
                    uint32_t t0,t1,t2,t3;
                    LDSM4(t0, t1, t2, t3, bufBh + off);
                    bh[2*p][0]=t0; bh[2*p][1]=t1; bh[2*p+1][0]=t2; bh[2*p+1][1]=t3;
                }
                #pragma unroll
                for (int mt = 0; mt < 2; mt++)
                    #pragma unroll
                    for (int nt = 0; nt < 8; nt++) {
                        MMA_F16(acc[mt][nt], ah[mt], bh[nt]);
                        MMA_F16(acc[mt][nt], al[mt], bh[nt]);
                    }
            }
        }
        if (s + 2 < nst) {
            __syncthreads();
            load_stage(sbase + (uint32_t)(s & 1)*ST_STRIDE, Ah, Al, Bh, soff,
                       aBase0 + (size_t)(s + 2)*64, bBase0 + (size_t)(s + 2)*64, K);
        }
    }

    #pragma unroll
    for (int mt = 0; mt < 2; mt++) {
        #pragma unroll
        for (int nt = 0; nt < 8; nt++) {
            int mrow = bm + m0 + mt*16 + (lane >> 2);
            int ncol = bn + n0 + nt*8 + ((lane & 3) << 1);
            #pragma unroll
            for (int half = 0; half < 2; half++) {
                int m = mrow + half*8;
                float v0 = acc[mt][nt][half*2 + 0];
                float v1 = acc[mt][nt][half*2 + 1];
                if (bias) { v0 += bias[ncol]; v1 += bias[ncol + 1]; }
                if (act)  { v0 = gelu_exact(v0); v1 = gelu_exact(v1); }
                if (res) {
                    const float2 rr = *(const float2*)(res + (size_t)m * N + ncol);
                    v0 += rr.x; v1 += rr.y;
                }
                if (C) {
                    float2 o; o.x = v0; o.y = v1;
                    *(float2*)(C + (size_t)m * N + ncol) = o;
                }
                if (Chi) {
                    uint32_t hh, ll;
                    split2h(v0, v1, hh, ll);
                    *(uint32_t*)(Chi + (size_t)m * N + ncol) = hh;
                    *(uint32_t*)(Clo + (size_t)m * N + ncol) = ll;
                }
            }
        }
    }
}

// ================ fused flash attention (HMMA) ==============================
// block: one (b,h) x 64 q rows; 128 threads. S=(Qh+Ql)Kh; O+=(Ph+Pl)Vh+Ph*Vl.
#define FA_SMEM 65536

__global__ __launch_bounds__(128)
void attn_fused(const __half* __restrict__ qh, const __half* __restrict__ ql,
                const __half* __restrict__ kh, const __half* __restrict__ vh,
                const __half* __restrict__ vl,
                __half* __restrict__ yhi, __half* __restrict__ ylo)
{
    const int qt = blockIdx.x & 7;
    const int bh = blockIdx.x >> 3;
    const int hh = bh & (Hq-1);
    const int bb = bh >> 4;
    const int q0 = qt * 64;
    const int tid = threadIdx.x, lane = tid & 31, w = tid >> 5;

    extern __shared__ char smem[];
    const uint32_t sb = smem_u32(smem);
    const uint32_t sQh = sb, sQl = sb + 8192u;

    const int lr = tid >> 1, lc = tid & 1;
    uint32_t ldst[4];
    #pragma unroll
    for (int i = 0; i < 4; i++)
        ldst[i] = SW128((uint32_t)(lr*128 + lc*64 + i*16));
    const size_t coloff = (size_t)hh*64 + lc*32;

    {   // Q tile
        size_t rb = ((size_t)(bb*Tq + q0 + lr))*Eq + coloff;
        #pragma unroll
        for (int i = 0; i < 4; i++) CP16(sQh + ldst[i], qh + rb + i*8);
        #pragma unroll
        for (int i = 0; i < 4; i++) CP16(sQl + ldst[i], ql + rb + i*8);
        CP_COMMIT();
    }
    {   // KV tile 0
        size_t rb = ((size_t)(bb*Tq + lr))*Eq + coloff;
        uint32_t kvb = sb + 16384u;
        #pragma unroll
        for (int i = 0; i < 4; i++) CP16(kvb + ldst[i],          kh + rb + i*8);
        #pragma unroll
        for (int i = 0; i < 4; i++) CP16(kvb + 8192u + ldst[i],  vh + rb + i*8);
        #pragma unroll
        for (int i = 0; i < 4; i++) CP16(kvb + 16384u + ldst[i], vl + rb + i*8);
        CP_COMMIT();
    }

    const int arow = w*16 + (lane & 15);
    const uint32_t aRow = (uint32_t)arow * 128u;
    const uint32_t aMask = (uint32_t)(arow & 7) << 4;
    const uint32_t kA = ((uint32_t)(lane >> 4)) << 4;
    uint32_t bRow[4], bMask[4];
    #pragma unroll
    for (int p = 0; p < 4; p++) {
        int r = p*16 + (((lane >> 4) & 1) << 3) + (lane & 7);
        bRow[p]  = (uint32_t)r * 128u;
        bMask[p] = (uint32_t)(r & 7) << 4;
    }
    const uint32_t kB = ((uint32_t)(lane & 8)) << 1;
    const int vsub = lane >> 3, vrow = lane & 7;
    const int vtok = ((vsub & 1) << 3) + vrow;
    const int vd   = (vsub >> 1) << 3;

    float o[8][4];
    #pragma unroll
    for (int nf = 0; nf < 8; nf++)
        #pragma unroll
        for (int e = 0; e < 4; e++) o[nf][e] = 0.f;
    float m0r = -1e30f, m1r = -1e30f, l0r = 0.f, l1r = 0.f;

    const int nkt = qt + 1;
    for (int kt = 0; kt < nkt; kt++) {
        CP_WAIT0();
        __syncthreads();
        if (kt + 1 < nkt) {
            size_t rb = ((size_t)(bb*Tq + (kt+1)*64 + lr))*Eq + coloff;
            uint32_t kvb = sb + 16384u + (uint32_t)((kt+1) & 1)*24576u;
            #pragma unroll
            for (int i = 0; i < 4; i++) CP16(kvb + ldst[i],          kh + rb + i*8);
            #pragma unroll
            for (int i = 0; i < 4; i++) CP16(kvb + 8192u + ldst[i],  vh + rb + i*8);
            #pragma unroll
            for (int i = 0; i < 4; i++) CP16(kvb + 16384u + ldst[i], vl + rb + i*8);
            CP_COMMIT();
        }
        const uint32_t kvb = sb + 16384u + (uint32_t)(kt & 1)*24576u;
        const uint32_t sK = kvb, sVh = kvb + 8192u, sVl = kvb + 16384u;

        float s[8][4];
        #pragma unroll
        for (int nf = 0; nf < 8; nf++)
            #pragma unroll
            for (int e = 0; e < 4; e++) s[nf][e] = 0.f;
        #pragma unroll
        for (int ks = 0; ks < 4; ks++) {
            uint32_t co = (uint32_t)(ks*32);
            uint32_t aoff = aRow + ((co + kA) ^ aMask);
            uint32_t ahr[4], alr[4];
            LDSM4(ahr[0], ahr[1], ahr[2], ahr[3], sQh + aoff);
            LDSM4(alr[0], alr[1], alr[2], alr[3], sQl + aoff);
            uint32_t bk[8][2];
            #pragma unroll
            for (int p = 0; p < 4; p++) {
                uint32_t off = bRow[p] + ((co + kB) ^ bMask[p]);
                uint32_t t0,t1,t2,t3;
                LDSM4(t0, t1, t2, t3, sK + off);
                bk[2*p][0]=t0; bk[2*p][1]=t1; bk[2*p+1][0]=t2; bk[2*p+1][1]=t3;
            }
            #pragma unroll
            for (int nf = 0; nf < 8; nf++) {
                MMA_F16(s[nf], ahr, bk[nf]);
                MMA_F16(s[nf], alr, bk[nf]);
            }
        }
        #pragma unroll
        for (int nf = 0; nf < 8; nf++)
            #pragma unroll
            for (int e = 0; e < 4; e++) s[nf][e] *= 0.125f;
        if (kt == qt) {
            int r0l = w*16 + (lane >> 2);
            #pragma unroll
            for (int nf = 0; nf < 8; nf++) {
                int col = nf*8 + ((lane & 3) << 1);
                if (col     > r0l)     s[nf][0] = -1e30f;
                if (col + 1 > r0l)     s[nf][1] = -1e30f;
                if (col     > r0l + 8) s[nf][2] = -1e30f;
                if (col + 1 > r0l + 8) s[nf][3] = -1e30f;
            }
        }
        float mx0 = -1e30f, mx1 = -1e30f;
        #pragma unroll
        for (int nf = 0; nf < 8; nf++) {
            mx0 = fmaxf(mx0, fmaxf(s[nf][0], s[nf][1]));
            mx1 = fmaxf(mx1, fmaxf(s[nf][2], s[nf][3]));
        }
        mx0 = fmaxf(mx0, __shfl_xor_sync(0xffffffffu, mx0, 1));
        mx0 = fmaxf(mx0, __shfl_xor_sync(0xffffffffu, mx0, 2));
        mx1 = fmaxf(mx1, __shfl_xor_sync(0xffffffffu, mx1, 1));
        mx1 = fmaxf(mx1, __shfl_xor_sync(0xffffffffu, mx1, 2));
        float mn0 = fmaxf(m0r, mx0), mn1 = fmaxf(m1r, mx1);
        float f0 = __expf(m0r - mn0), f1 = __expf(m1r - mn1);
        m0r = mn0; m1r = mn1;
        float ps0 = 0.f, ps1 = 0.f;
        #pragma unroll
        for (int nf = 0; nf < 8; nf++) {
            s[nf][0] = __expf(s[nf][0] - mn0); ps0 += s[nf][0];
            s[nf][1] = __expf(s[nf][1] - mn0); ps0 += s[nf][1];
            s[nf][2] = __expf(s[nf][2] - mn1); ps1 += s[nf][2];
            s[nf][3] = __expf(s[nf][3] - mn1); ps1 += s[nf][3];
        }
        ps0 += __shfl_xor_sync(0xffffffffu, ps0, 1);
        ps0 += __shfl_xor_sync(0xffffffffu, ps0, 2);
        ps1 += __shfl_xor_sync(0xffffffffu, ps1, 1);
        ps1 += __shfl_xor_sync(0xffffffffu, ps1, 2);
        l0r = l0r*f0 + ps0;
        l1r = l1r*f1 + ps1;
        #pragma unroll
        for (int nf = 0; nf < 8; nf++) {
            o[nf][0] *= f0; o[nf][1] *= f0;
            o[nf][2] *= f1; o[nf][3] *= f1;
        }
        #pragma unroll
        for (int kf = 0; kf < 4; kf++) {
            uint32_t ph[4], pl[4];
            split2h(s[2*kf][0],   s[2*kf][1],   ph[0], pl[0]);
            split2h(s[2*kf][2],   s[2*kf][3],   ph[1], pl[1]);
            split2h(s[2*kf+1][0], s[2*kf+1][1], ph[2], pl[2]);
            split2h(s[2*kf+1][2], s[2*kf+1][3], ph[3], pl[3]);
            int tok = kf*16 + vtok;
            uint32_t vrowoff = (uint32_t)tok * 128u;
            uint32_t vmask   = (uint32_t)(tok & 7) << 4;
            #pragma unroll
            for (int dw = 0; dw < 4; dw++) {
                uint32_t voff = vrowoff + (((uint32_t)((dw*16 + vd)*2)) ^ vmask);
                uint32_t h0,h1,h2,h3, g0,g1,g2,g3;
                LDSM4T(h0, h1, h2, h3, sVh + voff);
                LDSM4T(g0, g1, g2, g3, sVl + voff);
                MMA_F16B(o[2*dw],   ph, h0, h1);
                MMA_F16B(o[2*dw],   pl, h0, h1);
                MMA_F16B(o[2*dw],   ph, g0, g1);
                MMA_F16B(o[2*dw+1], ph, h2, h3);
                MMA_F16B(o[2*dw+1], pl, h2, h3);
                MMA_F16B(o[2*dw+1], ph, g2, g3);
            }
        }
    }

    float inv0 = 1.f / l0r, inv1 = 1.f / l1r;
    int row0 = q0 + w*16 + (lane >> 2);
    size_t base0 = ((size_t)(bb*Tq + row0))*Eq + (size_t)hh*64 + ((lane & 3) << 1);
    size_t base1 = base0 + (size_t)8*Eq;
    #pragma unroll
    for (int nf = 0; nf < 8; nf++) {
        uint32_t hv, lv;
        split2h(o[nf][0]*inv0, o[nf][1]*inv0, hv, lv);
        *(uint32_t*)(yhi + base0 + nf*8) = hv;
        *(uint32_t*)(ylo + base0 + nf*8) = lv;
        split2h(o[nf][2]*inv1, o[nf][3]*inv1, hv, lv);
        *(uint32_t*)(yhi + base1 + nf*8) = hv;
        *(uint32_t*)(ylo + base1 + nf*8) = lv;
    }
}

// ---------------- host orchestration ----------------------------------------
extern "C" void kernel_launch(void* const* d_in, const int* in_sizes, int n_in,
                              void* d_out, int out_size)
{
    const int*   x      = (const int*)  d_in[0];
    const float* tok    = (const float*)d_in[2];
    const float* pos    = (const float*)d_in[3];
    const float* ln1g   = (const float*)d_in[4];
    const float* ln1b   = (const float*)d_in[5];
    const float* Wqp    = (const float*)d_in[6];
    const float* bqp    = (const float*)d_in[7];
    const float* Wkp    = (const float*)d_in[8];
    const float* bkp    = (const float*)d_in[9];
    const float* Wvp    = (const float*)d_in[10];
    const float* bvp    = (const float*)d_in[11];
    const float* Wpp    = (const float*)d_in[12];
    const float* bpp    = (const float*)d_in[13];
    const float* ln2g   = (const float*)d_in[14];
    const float* ln2b   = (const float*)d_in[15];
    const float* Wf1p   = (const float*)d_in[16];
    const float* bf1p   = (const float*)d_in[17];
    const float* Wf2p   = (const float*)d_in[18];
    const float* bf2p   = (const float*)d_in[19];
    const float* lnfg   = (const float*)d_in[20];
    const float* lnfb   = (const float*)d_in[21];
    const float* headw  = (const float*)d_in[22];

    float *h;
    cudaGetSymbolAddress((void**)&h, g_h);

    __half *xnh,*xnl,*qhh,*qll,*khh,*kll,*vhh,*vll,*yh,*yl,*mlh,*mll;
    cudaGetSymbolAddress((void**)&xnh, g_xn_hi);
    cudaGetSymbolAddress((void**)&xnl, g_xn_lo);
    cudaGetSymbolAddress((void**)&qhh, g_q_hi);
    cudaGetSymbolAddress((void**)&qll, g_q_lo);
    cudaGetSymbolAddress((void**)&khh, g_k_hi);
    cudaGetSymbolAddress((void**)&kll, g_k_lo);
    cudaGetSymbolAddress((void**)&vhh, g_v_hi);
    cudaGetSymbolAddress((void**)&vll, g_v_lo);
    cudaGetSymbolAddress((void**)&yh,  g_y_hi);
    cudaGetSymbolAddress((void**)&yl,  g_y_lo);
    cudaGetSymbolAddress((void**)&mlh, g_ml_hi);
    cudaGetSymbolAddress((void**)&mll, g_ml_lo);

    __half *wq,*wk,*wv,*wp,*w1,*w2,*wh;
    cudaGetSymbolAddress((void**)&wq, g_wq);
    cudaGetSymbolAddress((void**)&wk, g_wk);
    cudaGetSymbolAddress((void**)&wv, g_wv);
    cudaGetSymbolAddress((void**)&wp, g_wp);
    cudaGetSymbolAddress((void**)&w1, g_w1);
    cudaGetSymbolAddress((void**)&w2, g_w2);
    cudaGetSymbolAddress((void**)&wh, g_wh);

    cudaFuncSetAttribute(gemm_hf, cudaFuncAttributeMaxDynamicSharedMemorySize, GT_SMEM);
    cudaFuncSetAttribute(attn_fused, cudaFuncAttributeMaxDynamicSharedMemorySize, FA_SMEM);

    convAll<<<147968, 256>>>(Wqp, Wkp, Wvp, Wpp, Wf1p, Wf2p, headw,
                             wq, wk, wv, wp, w1, w2, wh);
    embed_kernel<<<Mq, 256>>>(x, tok, pos, h);

    dim3 gEE(Eq/128, Mq/128);
    dim3 gEF(Fq/128, Mq/128);
    dim3 gEV(Vq/128, Mq/128);

    for (int l = 0; l < Lq; l++) {
        const size_t oE = (size_t)l*Eq*Eq;
        const size_t oF = (size_t)l*Eq*Fq;

        ln_kernel<<<Mq, 256>>>(h, ln1g + l*Eq, ln1b + l*Eq, xnh, xnl);
        gemm_hf<<<gEE, 256, GT_SMEM>>>(xnh, xnl, wq+oE, bqp + l*Eq, nullptr,
                                       nullptr, qhh, qll, Mq, Eq, Eq, 0);
        gemm_hf<<<gEE, 256, GT_SMEM>>>(xnh, xnl, wk+oE, bkp + l*Eq, nullptr,
                                       nullptr, khh, kll, Mq, Eq, Eq, 0);
        gemm_hf<<<gEE, 256, GT_SMEM>>>(xnh, xnl, wv+oE, bvp + l*Eq, nullptr,
                                       nullptr, vhh, vll, Mq, Eq, Eq, 0);

        attn_fused<<<Bq*Hq*8, 128, FA_SMEM>>>(qhh, qll, khh, vhh, vll, yh, yl);

        gemm_hf<<<gEE, 256, GT_SMEM>>>(yh, yl, wp+oE, bpp + l*Eq, h,
                                       h, nullptr, nullptr, Mq, Eq, Eq, 0);

        ln_kernel<<<Mq, 256>>>(h, ln2g + l*Eq, ln2b + l*Eq, xnh, xnl);
        gemm_hf<<<gEF, 256, GT_SMEM>>>(xnh, xnl, w1+oF, bf1p + l*Fq, nullptr,
                                       nullptr, mlh, mll, Mq, Fq, Eq, 1);
        gemm_hf<<<gEE, 256, GT_SMEM>>>(mlh, mll, w2+oF, bf2p + l*Eq, h,
                                       h, nullptr, nullptr, Mq, Eq, Fq, 0);
    }

    ln_kernel<<<Mq, 256>>>(h, lnfg, lnfb, xnh, xnl);
    gemm_hf<<<gEV, 256, GT_SMEM>>>(xnh, xnl, wh, nullptr, nullptr,
                                   (float*)d_out, nullptr, nullptr, Mq, Vq, Eq, 0);
}

// round 8
// speedup vs baseline: 1.6876x; 1.0006x over previous
#include <cuda_runtime.h>
#include <cuda_fp16.h>
#include <math.h>
#include <stdint.h>

#define Lq 12
#define Eq 1024
#define Hq 16
#define Tq 512
#define Bq 8
#define Vq 512
#define Fq 4096
#define Dq 64
#define Mq (Bq*Tq)

// ---------------- scratch ----------------------------------------------------
__device__ float g_h[Mq*Eq];
__device__ __half g_xn_hi[Mq*Eq],  g_xn_lo[Mq*Eq];
__device__ __half g_q_hi [Mq*Eq],  g_q_lo [Mq*Eq];
__device__ __half g_k_hi [Mq*Eq],  g_k_lo [Mq*Eq];
__device__ __half g_v_hi [Mq*Eq],  g_v_lo [Mq*Eq];
__device__ __half g_y_hi [Mq*Eq],  g_y_lo [Mq*Eq];
__device__ __half g_ml_hi[(size_t)Mq*Fq], g_ml_lo[(size_t)Mq*Fq];
__device__ __half g_wq[(size_t)Lq*Eq*Eq];
__device__ __half g_wk[(size_t)Lq*Eq*Eq];
__device__ __half g_wv[(size_t)Lq*Eq*Eq];
__device__ __half g_wp[(size_t)Lq*Eq*Eq];
__device__ __half g_w1[(size_t)Lq*Eq*Fq];
__device__ __half g_w2[(size_t)Lq*Fq*Eq];
__device__ __half g_wh[(size_t)Eq*Vq];

// ---------------- helpers ----------------------------------------------------
__device__ __forceinline__ uint32_t smem_u32(const void* p) {
    uint32_t a;
    asm("{ .reg .u64 t; cvta.to.shared.u64 t, %1; cvt.u32.u64 %0, t; }" : "=r"(a) : "l"(p));
    return a;
}
#define SW128(o) ((o) ^ (((o) >> 3) & 0x70))
#define CP16(dst, src) \
    asm volatile("cp.async.cg.shared.global [%0], [%1], 16;" :: "r"(dst), "l"(src) : "memory")
#define CP_COMMIT() asm volatile("cp.async.commit_group;" ::: "memory")
#define CP_WAIT1()  asm volatile("cp.async.wait_group 1;" ::: "memory")
#define CP_WAIT0()  asm volatile("cp.async.wait_group 0;" ::: "memory")
#define LDSM4(r0, r1, r2, r3, addr) \
    asm volatile("ldmatrix.sync.aligned.m8n8.x4.shared.b16 {%0,%1,%2,%3}, [%4];" \
                 : "=r"(r0), "=r"(r1), "=r"(r2), "=r"(r3) : "r"(addr))
#define LDSM4T(r0, r1, r2, r3, addr) \
    asm volatile("ldmatrix.sync.aligned.m8n8.x4.trans.shared.b16 {%0,%1,%2,%3}, [%4];" \
                 : "=r"(r0), "=r"(r1), "=r"(r2), "=r"(r3) : "r"(addr))
#define MMA_F16(c, a, b) \
    asm volatile("mma.sync.aligned.m16n8k16.row.col.f32.f16.f16.f32 " \
                 "{%0,%1,%2,%3}, {%4,%5,%6,%7}, {%8,%9}, {%0,%1,%2,%3};" \
                 : "+f"((c)[0]), "+f"((c)[1]), "+f"((c)[2]), "+f"((c)[3]) \
                 : "r"((a)[0]), "r"((a)[1]), "r"((a)[2]), "r"((a)[3]), \
                   "r"((b)[0]), "r"((b)[1]))
#define MMA_F16B(c, a, b0, b1) \
    asm volatile("mma.sync.aligned.m16n8k16.row.col.f32.f16.f16.f32 " \
                 "{%0,%1,%2,%3}, {%4,%5,%6,%7}, {%8,%9}, {%0,%1,%2,%3};" \
                 : "+f"((c)[0]), "+f"((c)[1]), "+f"((c)[2]), "+f"((c)[3]) \
                 : "r"((a)[0]), "r"((a)[1]), "r"((a)[2]), "r"((a)[3]), \
                   "r"(b0), "r"(b1))

__device__ __forceinline__ void split2h(float x, float y, uint32_t& h, uint32_t& l) {
    asm("cvt.rn.f16x2.f32 %0, %1, %2;" : "=r"(h) : "f"(y), "f"(x));
    __half2 hh = *reinterpret_cast<__half2*>(&h);
    float hx = __low2float(hh), hy = __high2float(hh);
    asm("cvt.rn.f16x2.f32 %0, %1, %2;" : "=r"(l) : "f"(y - hy), "f"(x - hx));
}

// ---------------- merged weight conversion -----------------------------------
__global__ __launch_bounds__(256)
void convAll(const float* __restrict__ Wq, const float* __restrict__ Wk,
             const float* __restrict__ Wv, const float* __restrict__ Wp,
             const float* __restrict__ W1, const float* __restrict__ W2,
             const float* __restrict__ Wh,
             __half* oq, __half* ok, __half* ov, __half* op,
             __half* o1, __half* o2, __half* oh)
{
    int b = blockIdx.x;
    const float* W; __half* O; int K, N;
    if (b < 49152) {
        int g = b / 12288; b -= g * 12288; K = Eq; N = Eq;
        W = (g==0) ? Wq : (g==1) ? Wk : (g==2) ? Wv : Wp;
        O = (g==0) ? oq : (g==1) ? ok : (g==2) ? ov : op;
    } else if (b < 98304)  { b -= 49152; K = Eq; N = Fq; W = W1; O = o1; }
    else if (b < 147456)   { b -= 98304; K = Fq; N = Eq; W = W2; O = o2; }
    else                   { b -= 147456; K = Eq; N = Vq; W = Wh; O = oh; }
    int tilesN = N >> 5;
    int per = tilesN * (K >> 5);
    int l = b / per; int rem = b - l * per;
    int kt = rem / tilesN, nt = rem - kt * tilesN;
    const float* Wl = W + (size_t)l * K * N;
    __half* Ol = O + (size_t)l * K * N;
    int k0 = kt * 32, n0 = nt * 32;
    __shared__ float t[32][33];
    int tid = threadIdx.x;
    int r = tid >> 5, c = tid & 31;
    #pragma unroll
    for (int i = 0; i < 4; i++)
        t[r + 8*i][c] = Wl[(size_t)(k0 + r + 8*i) * N + n0 + c];
    __syncthreads();
    #pragma unroll
    for (int i = 0; i < 4; i++)
        Ol[(size_t)(n0 + r + 8*i) * K + k0 + c] = __float2half(t[c][r + 8*i]);
}

// ---------------- embedding ---------------------------------------------------
__global__ void embed_kernel(const int* __restrict__ x,
                             const float* __restrict__ tok,
                             const float* __restrict__ pos,
                             float* __restrict__ out)
{
    int row = blockIdx.x;
    int t   = row & (Tq-1);
    int id  = x[row];
    int tid = threadIdx.x;
    float4 a = ((const float4*)(tok + (size_t)id*Eq))[tid];
    float4 p = ((const float4*)(pos + (size_t)t*Eq))[tid];
    float4 o; o.x=a.x+p.x; o.y=a.y+p.y; o.z=a.z+p.z; o.w=a.w+p.w;
    ((float4*)(out + (size_t)row*Eq))[tid] = o;
}

// ---------------- layernorm ---------------------------------------------------
__global__ void ln_kernel(const float* __restrict__ x,
                          const float* __restrict__ g,
                          const float* __restrict__ b,
                          __half* __restrict__ ohi,
                          __half* __restrict__ olo)
{
    int row = blockIdx.x;
    int tid = threadIdx.x;
    const float4* xr = (const float4*)(x + (size_t)row*Eq);
    float4 xv = xr[tid];
    float s  = xv.x + xv.y + xv.z + xv.w;
    float sq = xv.x*xv.x + xv.y*xv.y + xv.z*xv.z + xv.w*xv.w;
    #pragma unroll
    for (int off = 16; off > 0; off >>= 1) {
        s  += __shfl_xor_sync(0xffffffffu, s,  off);
        sq += __shfl_xor_sync(0xffffffffu, sq, off);
    }
    __shared__ float r1[8], r2[8];
    int w = tid >> 5;
    if ((tid & 31) == 0) { r1[w] = s; r2[w] = sq; }
    __syncthreads();
    float ts = 0.f, tq = 0.f;
    #pragma unroll
    for (int i = 0; i < 8; i++) { ts += r1[i]; tq += r2[i]; }
    float mean = ts * (1.0f/Eq);
    float var  = tq * (1.0f/Eq) - mean*mean;
    float rstd = rsqrtf(var + 1e-5f);
    float4 gv = ((const float4*)g)[tid];
    float4 bv = ((const float4*)b)[tid];
    float4 ov;
    ov.x = (xv.x-mean)*rstd*gv.x + bv.x;
    ov.y = (xv.y-mean)*rstd*gv.y + bv.y;
    ov.z = (xv.z-mean)*rstd*gv.z + bv.z;
    ov.w = (xv.w-mean)*rstd*gv.w + bv.w;
    uint32_t h0,h1,l0,l1;
    split2h(ov.x, ov.y, h0, l0);
    split2h(ov.z, ov.w, h1, l1);
    uint2 hv; hv.x = h0; hv.y = h1;
    uint2 lv; lv.x = l0; lv.y = l1;
    ((uint2*)(ohi + (size_t)row*Eq))[tid] = hv;
    ((uint2*)(olo + (size_t)row*Eq))[tid] = lv;
}

// ================ HMMA fp16 GEMM (2-stage, 2 CTAs/SM) =======================
#define ST_STRIDE 49152u
#define GT_SMEM (2*49152)

__device__ __forceinline__ float gelu_exact(float v) {
    return 0.5f * v * (1.0f + erff(v * 0.7071067811865475f));
}

__device__ __forceinline__ void load_stage(
    uint32_t sb, const __half* __restrict__ Ah, const __half* __restrict__ Al,
    const __half* __restrict__ Bh, const uint32_t* soff,
    size_t aBase, size_t bBase, int K)
{
    #pragma unroll
    for (int c = 0; c < 4; c++) {
        size_t ao = aBase + (size_t)(32*c) * K;
        size_t bo = bBase + (size_t)(32*c) * K;
        CP16(sb + soff[c],          Ah + ao);
        CP16(sb + 16384u + soff[c], Al + ao);
        CP16(sb + 32768u + soff[c], Bh + bo);
    }
    CP_COMMIT();
}

__global__ __launch_bounds__(256, 2)
void gemm_hf(const __half* __restrict__ Ah, const __half* __restrict__ Al,
             const __half* __restrict__ Bh,
             const float* __restrict__ bias, const float* __restrict__ res,
             float* __restrict__ C, __half* __restrict__ Chi,
             __half* __restrict__ Clo, int M, int N, int K, int act)
{
    extern __shared__ char smem[];
    const uint32_t sbase = smem_u32(smem);
    const int tid  = threadIdx.x;
    const int wid  = tid >> 5;
    const int lane = tid & 31;
    const int bm = blockIdx.y * 128;
    const int bn = blockIdx.x * 128;

    uint32_t soff[4];
    #pragma unroll
    for (int c = 0; c < 4; c++)
        soff[c] = SW128((uint32_t)((32*c + (tid >> 3))*128 + (tid & 7)*16));
    const size_t aBase0 = (size_t)(bm + (tid >> 3)) * K + (tid & 7)*8;
    const size_t bBase0 = (size_t)(bn + (tid >> 3)) * K + (tid & 7)*8;

    const int m0 = (wid & 3) * 32;
    const int n0 = (wid >> 2) * 64;
    uint32_t aRow[2], aMask[2];
    #pragma unroll
    for (int mt = 0; mt < 2; mt++) {
        int r = m0 + mt*16 + (lane & 15);
        aRow[mt]  = (uint32_t)r * 128u;
        aMask[mt] = (uint32_t)(r & 7) << 4;
    }
    const uint32_t kA = ((uint32_t)(lane >> 4)) << 4;
    uint32_t bRow[4], bMask[4];
    #pragma unroll
    for (int p = 0; p < 4; p++) {
        int r = n0 + p*16 + (((lane >> 4) & 1) << 3) + (lane & 7);
        bRow[p]  = (uint32_t)r * 128u;
        bMask[p] = (uint32_t)(r & 7) << 4;
    }
    const uint32_t kB = ((uint32_t)(lane & 8)) << 1;

    float acc[2][8][4];
    #pragma unroll
    for (int mt = 0; mt < 2; mt++)
        #pragma unroll
        for (int nt = 0; nt < 8; nt++)
            #pragma unroll
            for (int c = 0; c < 4; c++) acc[mt][nt][c] = 0.f;

    const int nst = K >> 6;
    load_stage(sbase, Ah, Al, Bh, soff, aBase0, bBase0, K);
    if (nst > 1)
        load_stage(sbase + ST_STRIDE, Ah, Al, Bh, soff, aBase0 + 64, bBase0 + 64, K);

    for (int s = 0; s < nst; s++) {
        if (s + 1 < nst) CP_WAIT1(); else CP_WAIT0();
        __syncthreads();
        {
            const uint32_t tb = sbase + (uint32_t)(s & 1)*ST_STRIDE;
            const uint32_t bufAh = tb, bufAl = tb + 16384u, bufBh = tb + 32768u;
            #pragma unroll
            for (int ks = 0; ks < 4; ks++) {
                uint32_t ah[2][4], al[2][4];
                #pragma unroll
                for (int mt = 0; mt < 2; mt++) {
                    uint32_t co  = (uint32_t)(ks*32) + kA;
                    uint32_t off = aRow[mt] + (co ^ aMask[mt]);
                    LDSM4(ah[mt][0], ah[mt][1], ah[mt][2], ah[mt][3], bufAh + off);
                    LDSM4(al[mt][0], al[mt][1], al[mt][2], al[mt][3], bufAl + off);
                }
                uint32_t bh[8][2];
                #pragma unroll
                for (int p = 0; p < 4; p++) {
                    uint32_t co  = (uint32_t)(ks*32) + kB;
                    uint32_t off = bRow[p] + (co ^ bMask[p]);
                    uint32_t t0,t1,t2,t3;
                    LDSM4(t0, t1, t2, t3, bufBh + off);
                    bh[2*p][0]=t0; bh[2*p][1]=t1; bh[2*p+1][0]=t2; bh[2*p+1][1]=t3;
                }
                #pragma unroll
                for (int mt = 0; mt < 2; mt++)
                    #pragma unroll
                    for (int nt = 0; nt < 8; nt++) {
                        MMA_F16(acc[mt][nt], ah[mt], bh[nt]);
                        MMA_F16(acc[mt][nt], al[mt], bh[nt]);
                    }
            }
        }
        if (s + 2 < nst) {
            __syncthreads();
            load_stage(sbase + (uint32_t)(s & 1)*ST_STRIDE, Ah, Al, Bh, soff,
                       aBase0 + (size_t)(s + 2)*64, bBase0 + (size_t)(s + 2)*64, K);
        }
    }

    #pragma unroll
    for (int mt = 0; mt < 2; mt++) {
        #pragma unroll
        for (int nt = 0; nt < 8; nt++) {
            int mrow = bm + m0 + mt*16 + (lane >> 2);
            int ncol = bn + n0 + nt*8 + ((lane & 3) << 1);
            #pragma unroll
            for (int half = 0; half < 2; half++) {
                int m = mrow + half*8;
                float v0 = acc[mt][nt][half*2 + 0];
                float v1 = acc[mt][nt][half*2 + 1];
                if (bias) { v0 += bias[ncol]; v1 += bias[ncol + 1]; }
                if (act)  { v0 = gelu_exact(v0); v1 = gelu_exact(v1); }
                if (res) {
                    const float2 rr = *(const float2*)(res + (size_t)m * N + ncol);
                    v0 += rr.x; v1 += rr.y;
                }
                if (C) {
                    float2 o; o.x = v0; o.y = v1;
                    *(float2*)(C + (size_t)m * N + ncol) = o;
                }
                if (Chi) {
                    uint32_t hh, ll;
                    split2h(v0, v1, hh, ll);
                    *(uint32_t*)(Chi + (size_t)m * N + ncol) = hh;
                    *(uint32_t*)(Clo + (size_t)m * N + ncol) = ll;
                }
            }
        }
    }
}

// ================ fused flash attention (HMMA) ==============================
// block: one (b,h) x 64 q rows; 128 threads. S=(Qh+Ql)Kh; O+=(Ph+Pl)Vh+Ph*Vl.
#define FA_SMEM 65536

__global__ __launch_bounds__(128)
void attn_fused(const __half* __restrict__ qh, const __half* __restrict__ ql,
                const __half* __restrict__ kh, const __half* __restrict__ vh,
                const __half* __restrict__ vl,
                __half* __restrict__ yhi, __half* __restrict__ ylo)
{
    const int qt = blockIdx.x & 7;
    const int bh = blockIdx.x >> 3;
    const int hh = bh & (Hq-1);
    const int bb = bh >> 4;
    const int q0 = qt * 64;
    const int tid = threadIdx.x, lane = tid & 31, w = tid >> 5;

    extern __shared__ char smem[];
    const uint32_t sb = smem_u32(smem);
    const uint32_t sQh = sb, sQl = sb + 8192u;

    const int lr = tid >> 1, lc = tid & 1;
    uint32_t ldst[4];
    #pragma unroll
    for (int i = 0; i < 4; i++)
        ldst[i] = SW128((uint32_t)(lr*128 + lc*64 + i*16));
    const size_t coloff = (size_t)hh*64 + lc*32;

    {   // Q tile
        size_t rb = ((size_t)(bb*Tq + q0 + lr))*Eq + coloff;
        #pragma unroll
        for (int i = 0; i < 4; i++) CP16(sQh + ldst[i], qh + rb + i*8);
        #pragma unroll
        for (int i = 0; i < 4; i++) CP16(sQl + ldst[i], ql + rb + i*8);
        CP_COMMIT();
    }
    {   // KV tile 0
        size_t rb = ((size_t)(bb*Tq + lr))*Eq + coloff;
        uint32_t kvb = sb + 16384u;
        #pragma unroll
        for (int i = 0; i < 4; i++) CP16(kvb + ldst[i],          kh + rb + i*8);
        #pragma unroll
        for (int i = 0; i < 4; i++) CP16(kvb + 8192u + ldst[i],  vh + rb + i*8);
        #pragma unroll
        for (int i = 0; i < 4; i++) CP16(kvb + 16384u + ldst[i], vl + rb + i*8);
        CP_COMMIT();
    }

    const int arow = w*16 + (lane & 15);
    const uint32_t aRow = (uint32_t)arow * 128u;
    const uint32_t aMask = (uint32_t)(arow & 7) << 4;
    const uint32_t kA = ((uint32_t)(lane >> 4)) << 4;
    uint32_t bRow[4], bMask[4];
    #pragma unroll
    for (int p = 0; p < 4; p++) {
        int r = p*16 + (((lane >> 4) & 1) << 3) + (lane & 7);
        bRow[p]  = (uint32_t)r * 128u;
        bMask[p] = (uint32_t)(r & 7) << 4;
    }
    const uint32_t kB = ((uint32_t)(lane & 8)) << 1;
    const int vsub = lane >> 3, vrow = lane & 7;
    const int vtok = ((vsub & 1) << 3) + vrow;
    const int vd   = (vsub >> 1) << 3;

    float o[8][4];
    #pragma unroll
    for (int nf = 0; nf < 8; nf++)
        #pragma unroll
        for (int e = 0; e < 4; e++) o[nf][e] = 0.f;
    float m0r = -1e30f, m1r = -1e30f, l0r = 0.f, l1r = 0.f;

    const int nkt = qt + 1;
    for (int kt = 0; kt < nkt; kt++) {
        CP_WAIT0();
        __syncthreads();
        if (kt + 1 < nkt) {
            size_t rb = ((size_t)(bb*Tq + (kt+1)*64 + lr))*Eq + coloff;
            uint32_t kvb = sb + 16384u + (uint32_t)((kt+1) & 1)*24576u;
            #pragma unroll
            for (int i = 0; i < 4; i++) CP16(kvb + ldst[i],          kh + rb + i*8);
            #pragma unroll
            for (int i = 0; i < 4; i++) CP16(kvb + 8192u + ldst[i],  vh + rb + i*8);
            #pragma unroll
            for (int i = 0; i < 4; i++) CP16(kvb + 16384u + ldst[i], vl + rb + i*8);
            CP_COMMIT();
        }
        const uint32_t kvb = sb + 16384u + (uint32_t)(kt & 1)*24576u;
        const uint32_t sK = kvb, sVh = kvb + 8192u, sVl = kvb + 16384u;

        float s[8][4];
        #pragma unroll
        for (int nf = 0; nf < 8; nf++)
            #pragma unroll
            for (int e = 0; e < 4; e++) s[nf][e] = 0.f;
        #pragma unroll
        for (int ks = 0; ks < 4; ks++) {
            uint32_t co = (uint32_t)(ks*32);
            uint32_t aoff = aRow + ((co + kA) ^ aMask);
            uint32_t ahr[4], alr[4];
            LDSM4(ahr[0], ahr[1], ahr[2], ahr[3], sQh + aoff);
            LDSM4(alr[0], alr[1], alr[2], alr[3], sQl + aoff);
            uint32_t bk[8][2];
            #pragma unroll
            for (int p = 0; p < 4; p++) {
                uint32_t off = bRow[p] + ((co + kB) ^ bMask[p]);
                uint32_t t0,t1,t2,t3;
                LDSM4(t0, t1, t2, t3, sK + off);
                bk[2*p][0]=t0; bk[2*p][1]=t1; bk[2*p+1][0]=t2; bk[2*p+1][1]=t3;
            }
            #pragma unroll
            for (int nf = 0; nf < 8; nf++) {
                MMA_F16(s[nf], ahr, bk[nf]);
                MMA_F16(s[nf], alr, bk[nf]);
            }
        }
        #pragma unroll
        for (int nf = 0; nf < 8; nf++)
            #pragma unroll
            for (int e = 0; e < 4; e++) s[nf][e] *= 0.125f;
        if (kt == qt) {
            int r0l = w*16 + (lane >> 2);
            #pragma unroll
            for (int nf = 0; nf < 8; nf++) {
                int col = nf*8 + ((lane & 3) << 1);
                if (col     > r0l)     s[nf][0] = -1e30f;
                if (col + 1 > r0l)     s[nf][1] = -1e30f;
                if (col     > r0l + 8) s[nf][2] = -1e30f;
                if (col + 1 > r0l + 8) s[nf][3] = -1e30f;
            }
        }
        float mx0 = -1e30f, mx1 = -1e30f;
        #pragma unroll
        for (int nf = 0; nf < 8; nf++) {
            mx0 = fmaxf(mx0, fmaxf(s[nf][0], s[nf][1]));
            mx1 = fmaxf(mx1, fmaxf(s[nf][2], s[nf][3]));
        }
        mx0 = fmaxf(mx0, __shfl_xor_sync(0xffffffffu, mx0, 1));
        mx0 = fmaxf(mx0, __shfl_xor_sync(0xffffffffu, mx0, 2));
        mx1 = fmaxf(mx1, __shfl_xor_sync(0xffffffffu, mx1, 1));
        mx1 = fmaxf(mx1, __shfl_xor_sync(0xffffffffu, mx1, 2));
        float mn0 = fmaxf(m0r, mx0), mn1 = fmaxf(m1r, mx1);
        float f0 = __expf(m0r - mn0), f1 = __expf(m1r - mn1);
        m0r = mn0; m1r = mn1;
        float ps0 = 0.f, ps1 = 0.f;
        #pragma unroll
        for (int nf = 0; nf < 8; nf++) {
            s[nf][0] = __expf(s[nf][0] - mn0); ps0 += s[nf][0];
            s[nf][1] = __expf(s[nf][1] - mn0); ps0 += s[nf][1];
            s[nf][2] = __expf(s[nf][2] - mn1); ps1 += s[nf][2];
            s[nf][3] = __expf(s[nf][3] - mn1); ps1 += s[nf][3];
        }
        ps0 += __shfl_xor_sync(0xffffffffu, ps0, 1);
        ps0 += __shfl_xor_sync(0xffffffffu, ps0, 2);
        ps1 += __shfl_xor_sync(0xffffffffu, ps1, 1);
        ps1 += __shfl_xor_sync(0xffffffffu, ps1, 2);
        l0r = l0r*f0 + ps0;
        l1r = l1r*f1 + ps1;
        #pragma unroll
        for (int nf = 0; nf < 8; nf++) {
            o[nf][0] *= f0; o[nf][1] *= f0;
            o[nf][2] *= f1; o[nf][3] *= f1;
        }
        #pragma unroll
        for (int kf = 0; kf < 4; kf++) {
            uint32_t ph[4], pl[4];
            split2h(s[2*kf][0],   s[2*kf][1],   ph[0], pl[0]);
            split2h(s[2*kf][2],   s[2*kf][3],   ph[1], pl[1]);
            split2h(s[2*kf+1][0], s[2*kf+1][1], ph[2], pl[2]);
            split2h(s[2*kf+1][2], s[2*kf+1][3], ph[3], pl[3]);
            int tok = kf*16 + vtok;
            uint32_t vrowoff = (uint32_t)tok * 128u;
            uint32_t vmask   = (uint32_t)(tok & 7) << 4;
            #pragma unroll
            for (int dw = 0; dw < 4; dw++) {
                uint32_t voff = vrowoff + (((uint32_t)((dw*16 + vd)*2)) ^ vmask);
                uint32_t h0,h1,h2,h3, g0,g1,g2,g3;
                LDSM4T(h0, h1, h2, h3, sVh + voff);
                LDSM4T(g0, g1, g2, g3, sVl + voff);
                MMA_F16B(o[2*dw],   ph, h0, h1);
                MMA_F16B(o[2*dw],   pl, h0, h1);
                MMA_F16B(o[2*dw],   ph, g0, g1);
                MMA_F16B(o[2*dw+1], ph, h2, h3);
                MMA_F16B(o[2*dw+1], pl, h2, h3);
                MMA_F16B(o[2*dw+1], ph, g2, g3);
            }
        }
    }

    float inv0 = 1.f / l0r, inv1 = 1.f / l1r;
    int row0 = q0 + w*16 + (lane >> 2);
    size_t base0 = ((size_t)(bb*Tq + row0))*Eq + (size_t)hh*64 + ((lane & 3) << 1);
    size_t base1 = base0 + (size_t)8*Eq;
    #pragma unroll
    for (int nf = 0; nf < 8; nf++) {
        uint32_t hv, lv;
        split2h(o[nf][0]*inv0, o[nf][1]*inv0, hv, lv);
        *(uint32_t*)(yhi + base0 + nf*8) = hv;
        *(uint32_t*)(ylo + base0 + nf*8) = lv;
        split2h(o[nf][2]*inv1, o[nf][3]*inv1, hv, lv);
        *(uint32_t*)(yhi + base1 + nf*8) = hv;
        *(uint32_t*)(ylo + base1 + nf*8) = lv;
    }
}

// ---------------- host orchestration ----------------------------------------
extern "C" void kernel_launch(void* const* d_in, const int* in_sizes, int n_in,
                              void* d_out, int out_size)
{
    const int*   x      = (const int*)  d_in[0];
    const float* tok    = (const float*)d_in[2];
    const float* pos    = (const float*)d_in[3];
    const float* ln1g   = (const float*)d_in[4];
    const float* ln1b   = (const float*)d_in[5];
    const float* Wqp    = (const float*)d_in[6];
    const float* bqp    = (const float*)d_in[7];
    const float* Wkp    = (const float*)d_in[8];
    const float* bkp    = (const float*)d_in[9];
    const float* Wvp    = (const float*)d_in[10];
    const float* bvp    = (const float*)d_in[11];
    const float* Wpp    = (const float*)d_in[12];
    const float* bpp    = (const float*)d_in[13];
    const float* ln2g   = (const float*)d_in[14];
    const float* ln2b   = (const float*)d_in[15];
    const float* Wf1p   = (const float*)d_in[16];
    const float* bf1p   = (const float*)d_in[17];
    const float* Wf2p   = (const float*)d_in[18];
    const float* bf2p   = (const float*)d_in[19];
    const float* lnfg   = (const float*)d_in[20];
    const float* lnfb   = (const float*)d_in[21];
    const float* headw  = (const float*)d_in[22];

    float *h;
    cudaGetSymbolAddress((void**)&h, g_h);

    __half *xnh,*xnl,*qhh,*qll,*khh,*kll,*vhh,*vll,*yh,*yl,*mlh,*mll;
    cudaGetSymbolAddress((void**)&xnh, g_xn_hi);
    cudaGetSymbolAddress((void**)&xnl, g_xn_lo);
    cudaGetSymbolAddress((void**)&qhh, g_q_hi);
    cudaGetSymbolAddress((void**)&qll, g_q_lo);
    cudaGetSymbolAddress((void**)&khh, g_k_hi);
    cudaGetSymbolAddress((void**)&kll, g_k_lo);
    cudaGetSymbolAddress((void**)&vhh, g_v_hi);
    cudaGetSymbolAddress((void**)&vll, g_v_lo);
    cudaGetSymbolAddress((void**)&yh,  g_y_hi);
    cudaGetSymbolAddress((void**)&yl,  g_y_lo);
    cudaGetSymbolAddress((void**)&mlh, g_ml_hi);
    cudaGetSymbolAddress((void**)&mll, g_ml_lo);

    __half *wq,*wk,*wv,*wp,*w1,*w2,*wh;
    cudaGetSymbolAddress((void**)&wq, g_wq);
    cudaGetSymbolAddress((void**)&wk, g_wk);
    cudaGetSymbolAddress((void**)&wv, g_wv);
    cudaGetSymbolAddress((void**)&wp, g_wp);
    cudaGetSymbolAddress((void**)&w1, g_w1);
    cudaGetSymbolAddress((void**)&w2, g_w2);
    cudaGetSymbolAddress((void**)&wh, g_wh);

    cudaFuncSetAttribute(gemm_hf, cudaFuncAttributeMaxDynamicSharedMemorySize, GT_SMEM);
    cudaFuncSetAttribute(attn_fused, cudaFuncAttributeMaxDynamicSharedMemorySize, FA_SMEM);

    convAll<<<147968, 256>>>(Wqp, Wkp, Wvp, Wpp, Wf1p, Wf2p, headw,
                             wq, wk, wv, wp, w1, w2, wh);
    embed_kernel<<<Mq, 256>>>(x, tok, pos, h);

    dim3 gEE(Eq/128, Mq/128);
    dim3 gEF(Fq/128, Mq/128);
    dim3 gEV(Vq/128, Mq/128);

    for (int l = 0; l < Lq; l++) {
        const size_t oE = (size_t)l*Eq*Eq;
        const size_t oF = (size_t)l*Eq*Fq;

        ln_kernel<<<Mq, 256>>>(h, ln1g + l*Eq, ln1b + l*Eq, xnh, xnl);
        gemm_hf<<<gEE, 256, GT_SMEM>>>(xnh, xnl, wq+oE, bqp + l*Eq, nullptr,
                                       nullptr, qhh, qll, Mq, Eq, Eq, 0);
        gemm_hf<<<gEE, 256, GT_SMEM>>>(xnh, xnl, wk+oE, bkp + l*Eq, nullptr,
                                       nullptr, khh, kll, Mq, Eq, Eq, 0);
        gemm_hf<<<gEE, 256, GT_SMEM>>>(xnh, xnl, wv+oE, bvp + l*Eq, nullptr,
                                       nullptr, vhh, vll, Mq, Eq, Eq, 0);

        attn_fused<<<Bq*Hq*8, 128, FA_SMEM>>>(qhh, qll, khh, vhh, vll, yh, yl);

        gemm_hf<<<gEE, 256, GT_SMEM>>>(yh, yl, wp+oE, bpp + l*Eq, h,
                                       h, nullptr, nullptr, Mq, Eq, Eq, 0);

        ln_kernel<<<Mq, 256>>>(h, ln2g + l*Eq, ln2b + l*Eq, xnh, xnl);
        gemm_hf<<<gEF, 256, GT_SMEM>>>(xnh, xnl, w1+oF, bf1p + l*Fq, nullptr,
                                       nullptr, mlh, mll, Mq, Fq, Eq, 1);
        gemm_hf<<<gEE, 256, GT_SMEM>>>(mlh, mll, w2+oF, bf2p + l*Eq, h,
                                       h, nullptr, nullptr, Mq, Eq, Fq, 0);
    }

    ln_kernel<<<Mq, 256>>>(h, lnfg, lnfb, xnh, xnl);
    gemm_hf<<<gEV, 256, GT_SMEM>>>(xnh, xnl, wh, nullptr, nullptr,
                                   (float*)d_out, nullptr, nullptr, Mq, Vq, Eq, 0);
}